// round 7
// baseline (speedup 1.0000x reference)
#include <cuda_runtime.h>
#include <cuda_bf16.h>
#include <cstdint>
#include <math.h>

#define BDIM 32
#define LDIM 8
#define SDIM 512
#define DDIM 256
#define EDIM 2048
#define NTOK (BDIM*LDIM*SDIM)   /* 131072 */
#define TOKL (BDIM*SDIM)        /* 16384 tokens per l */

// ---- device scratch ----
__device__ float      g_embedT[(size_t)LDIM*EDIM*DDIM];   // (L,E,D) fp32 codebook
__device__ float      g_enorm [(size_t)LDIM*EDIM];        // ||e||^2 fp32
__device__ int        g_ids   [NTOK];
__device__ int2       g_cand  [NTOK];                     // top-2 approx candidates
__device__ int        g_counts[(size_t)LDIM*EDIM];
__device__ long long  g_sum   [(size_t)LDIM*DDIM*EDIM];
__device__ unsigned long long g_diffacc;
__device__ float      g_nvals [LDIM];
// bf16 2-split planes
__device__ unsigned short g_A1[(size_t)NTOK*DDIM];
__device__ unsigned short g_A2[(size_t)NTOK*DDIM];
__device__ unsigned short g_B1[(size_t)LDIM*EDIM*DDIM];
__device__ unsigned short g_B2[(size_t)LDIM*EDIM*DDIM];

// =====================================================================
__device__ __forceinline__ uint32_t smem_addr_u32(const void* p) {
    uint32_t a;
    asm("{ .reg .u64 t; cvta.to.shared.u64 t, %1; cvt.u32.u64 %0, t; }" : "=r"(a) : "l"(p));
    return a;
}
__device__ __forceinline__ void cpasync16(uint32_t s, const void* g) {
    asm volatile("cp.async.cg.shared.global [%0], [%1], 16;" :: "r"(s), "l"(g));
}
#define CP_COMMIT() asm volatile("cp.async.commit_group;" ::: "memory")
#define CP_WAIT(n)  asm volatile("cp.async.wait_group %0;" :: "n"(n) : "memory")

__device__ __forceinline__ void ldsm4(uint32_t* r, uint32_t addr) {
    asm volatile("ldmatrix.sync.aligned.m8n8.x4.shared.b16 {%0,%1,%2,%3}, [%4];"
        : "=r"(r[0]), "=r"(r[1]), "=r"(r[2]), "=r"(r[3]) : "r"(addr));
}
__device__ __forceinline__ void mma16816(float* c, const uint32_t* a, uint32_t b0, uint32_t b1) {
    asm volatile("mma.sync.aligned.m16n8k16.row.col.f32.bf16.bf16.f32 "
        "{%0,%1,%2,%3}, {%4,%5,%6,%7}, {%8,%9}, {%0,%1,%2,%3};"
        : "+f"(c[0]), "+f"(c[1]), "+f"(c[2]), "+f"(c[3])
        : "r"(a[0]), "r"(a[1]), "r"(a[2]), "r"(a[3]), "r"(b0), "r"(b1));
}

__device__ __forceinline__ void split2(float v, unsigned short& a, unsigned short& b) {
    __nv_bfloat16 h1 = __float2bfloat16(v);
    float r1 = v - __bfloat162float(h1);
    __nv_bfloat16 h2 = __float2bfloat16(r1);
    a = __bfloat16_as_ushort(h1);
    b = __bfloat16_as_ushort(h2);
}

// Expand x -> A1, A2
__global__ void k_expand_x(const float* __restrict__ x) {
    int t = blockIdx.x;
    int i = threadIdx.x;           // 128 threads, 2 d each
    float2 v = *(const float2*)(x + (size_t)t*DDIM + 2*i);
    unsigned short a0,b0, a1,b1;
    split2(v.x, a0, b0);
    split2(v.y, a1, b1);
    size_t o = (size_t)t*(DDIM/2) + i;
    ((uint32_t*)g_A1)[o] = (uint32_t)a0 | ((uint32_t)a1 << 16);
    ((uint32_t*)g_A2)[o] = (uint32_t)b0 | ((uint32_t)b1 << 16);
}

// Transpose + expand embed -> B1, B2 + fp32 g_embedT
__global__ void k_expand_e(const float* __restrict__ embed) {
    __shared__ float tile[32][33];
    int l  = blockIdx.z;
    int e0 = blockIdx.x * 32;
    int d0 = blockIdx.y * 32;
    int tx = threadIdx.x, ty = threadIdx.y;   // 32 x 8
    const float* src = embed + (size_t)l*DDIM*EDIM;
    #pragma unroll
    for (int i = ty; i < 32; i += 8)
        tile[i][tx] = src[(size_t)(d0+i)*EDIM + e0 + tx];
    __syncthreads();
    #pragma unroll
    for (int i = ty; i < 32; i += 8) {
        float v = tile[tx][i];
        unsigned short h1, h2;
        split2(v, h1, h2);
        size_t idx = ((size_t)(l*EDIM + e0 + i))*DDIM + (d0 + tx);
        g_B1[idx] = h1; g_B2[idx] = h2;
        g_embedT[idx] = v;
    }
}

__global__ void k_enorm(const float* __restrict__ embed) {
    int idx = blockIdx.x*blockDim.x + threadIdx.x;
    int l = idx / EDIM, e = idx % EDIM;
    const float* src = embed + (size_t)l*DDIM*EDIM + e;
    float s = 0.f;
    #pragma unroll 8
    for (int d = 0; d < DDIM; d++) {
        float v = src[(size_t)d*EDIM];
        s += v*v;
    }
    g_enorm[idx] = s;
}

// =====================================================================
// HMMA fused GEMM + approx top-2. 128 tokens x 2048 codes per CTA.
// 3-stage cp.async ring, depth-2 prefetch, k-slabs of 32 (A and B both
// slabbed). 80B row pad -> conflict-free ldmatrix. 3 products A1B1+A1B2+A2B1.
// Stage layout: A1@0(10240) A2@10240 B1@20480(20480) B2@40960. Stage=61440.
// =====================================================================
#define ST_A2   10240
#define ST_B1   20480
#define ST_B2   40960
#define STAGE   61440
#define SMEM_TOTAL (3*STAGE)

__device__ __forceinline__ void load_slab(uint32_t dst,
        const unsigned short* A1r, const unsigned short* A2r,
        const unsigned short* B1r, const unsigned short* B2r, int g, int tid) {
    int n0 = (g >> 3) << 8, kcol = (g & 7) << 5;
    #pragma unroll
    for (int it = 0; it < 2; it++) {          // A planes: 512 chunks each
        int c = it*256 + tid, row = c >> 2, q = c & 3;
        const size_t go = (size_t)row*DDIM + kcol + q*8;
        uint32_t so = row*80 + q*16;
        cpasync16(dst + so,         A1r + go);
        cpasync16(dst + ST_A2 + so, A2r + go);
    }
    #pragma unroll
    for (int it = 0; it < 4; it++) {          // B planes: 1024 chunks each
        int c = it*256 + tid, row = c >> 2, q = c & 3;
        const size_t go = (size_t)(n0 + row)*DDIM + kcol + q*8;
        uint32_t so = row*80 + q*16;
        cpasync16(dst + ST_B1 + so, B1r + go);
        cpasync16(dst + ST_B2 + so, B2r + go);
    }
}

__global__ void __launch_bounds__(256)
k_assign_mma(int dummy) {
    extern __shared__ unsigned char smem[];
    const uint32_t sb = smem_addr_u32(smem);
    int tid = threadIdx.x, lane = tid & 31, wid = tid >> 5;
    int wm = wid >> 2, wn = wid & 3;
    int l  = blockIdx.y;
    int r0 = blockIdx.x * 128;
    int b = r0 >> 9, s0 = r0 & 511;
    size_t tokbase = ((size_t)(b*LDIM + l)*SDIM + s0);

    const unsigned short* A1r = g_A1 + tokbase*DDIM;
    const unsigned short* A2r = g_A2 + tokbase*DDIM;
    const unsigned short* B1r = g_B1 + (size_t)l*EDIM*DDIM;
    const unsigned short* B2r = g_B2 + (size_t)l*EDIM*DDIM;
    const float* en = g_enorm + l*EDIM;

    // prologue: slabs 0 and 1 in flight
    load_slab(sb,         A1r, A2r, B1r, B2r, 0, tid); CP_COMMIT();
    load_slab(sb + STAGE, A1r, A2r, B1r, B2r, 1, tid); CP_COMMIT();

    float bv0[8], bv1[8]; int bi0[8], bi1[8];
    #pragma unroll
    for (int i = 0; i < 8; i++) { bv0[i] = 3.4e38f; bv1[i] = 3.4e38f; bi0[i] = 0; bi1[i] = 0; }

    const uint32_t aAddr = (uint32_t)((wm*64 + (lane & 15))*80 + (lane >> 4)*16);
    const uint32_t bAddr = (uint32_t)(ST_B1 + (wn*64 + (lane & 7) + ((lane >> 4) & 1)*8)*80
                                      + ((lane >> 3) & 1)*16);
    float acc[4][8][4];
    uint32_t stageOff[3] = {0u, (uint32_t)STAGE, (uint32_t)(2*STAGE)};

    int stage = 0;
    for (int g = 0; g < 64; g++) {
        int ks = g & 7;
        if (ks == 0) {
            #pragma unroll
            for (int mf = 0; mf < 4; mf++)
                #pragma unroll
                for (int nf = 0; nf < 8; nf++)
                    #pragma unroll
                    for (int q = 0; q < 4; q++) acc[mf][nf][q] = 0.f;
        }
        CP_WAIT(1);                // slab g complete (g+1 still pending)
        __syncthreads();

        uint32_t stB = sb + stageOff[stage];
        uint32_t aB = stB + aAddr;
        uint32_t bB = stB + bAddr;
        #pragma unroll
        for (int kq = 0; kq < 2; kq++) {
            uint32_t a[4][4], bf[4][4], bf2[4][4];
            #pragma unroll
            for (int mf = 0; mf < 4; mf++) ldsm4(a[mf],   aB + mf*1280 + kq*32);
            #pragma unroll
            for (int nf = 0; nf < 4; nf++) ldsm4(bf[nf],  bB + nf*1280 + kq*32);
            #pragma unroll
            for (int nf = 0; nf < 4; nf++) ldsm4(bf2[nf], bB + (ST_B2-ST_B1) + nf*1280 + kq*32);
            #pragma unroll
            for (int mf = 0; mf < 4; mf++)
                #pragma unroll
                for (int nf = 0; nf < 4; nf++) {
                    mma16816(acc[mf][2*nf],   a[mf], bf[nf][0],  bf[nf][1]);
                    mma16816(acc[mf][2*nf+1], a[mf], bf[nf][2],  bf[nf][3]);
                    mma16816(acc[mf][2*nf],   a[mf], bf2[nf][0], bf2[nf][1]);
                    mma16816(acc[mf][2*nf+1], a[mf], bf2[nf][2], bf2[nf][3]);
                }
            #pragma unroll
            for (int mf = 0; mf < 4; mf++) ldsm4(a[mf], aB + ST_A2 + mf*1280 + kq*32);
            #pragma unroll
            for (int mf = 0; mf < 4; mf++)
                #pragma unroll
                for (int nf = 0; nf < 4; nf++) {
                    mma16816(acc[mf][2*nf],   a[mf], bf[nf][0], bf[nf][1]);
                    mma16816(acc[mf][2*nf+1], a[mf], bf[nf][2], bf[nf][3]);
                }
        }

        if (ks == 7) {
            int n0 = (g >> 3) << 8;
            #pragma unroll
            for (int nf = 0; nf < 8; nf++) {
                int col = n0 + wn*64 + nf*8 + 2*(lane & 3);
                float e0 = en[col], e1 = en[col + 1];
                #pragma unroll
                for (int mf = 0; mf < 4; mf++)
                    #pragma unroll
                    for (int h = 0; h < 2; h++) {
                        int s = mf*2 + h;
                        float v0 = fmaf(-2.0f, acc[mf][nf][2*h],     e0);
                        float v1 = fmaf(-2.0f, acc[mf][nf][2*h + 1], e1);
                        if (v0 < bv0[s]) { bv1[s]=bv0[s]; bi1[s]=bi0[s]; bv0[s]=v0; bi0[s]=col; }
                        else if (v0 < bv1[s]) { bv1[s]=v0; bi1[s]=col; }
                        if (v1 < bv0[s]) { bv1[s]=bv0[s]; bi1[s]=bi0[s]; bv0[s]=v1; bi0[s]=col+1; }
                        else if (v1 < bv1[s]) { bv1[s]=v1; bi1[s]=col+1; }
                    }
            }
        }

        __syncthreads();           // everyone done reading stage (g%3) buffers
        if (g + 2 < 64) {
            int nstage = stage + 2; if (nstage >= 3) nstage -= 3;
            load_slab(sb + stageOff[nstage], A1r, A2r, B1r, B2r, g + 2, tid);
        }
        CP_COMMIT();               // empty group at tail keeps wait count valid
        stage = (stage + 1 == 3) ? 0 : stage + 1;
    }

    __syncthreads();
    float* redV = (float*)smem;                 // [128][16][2]
    int*   redI = (int*)(smem + 16384);
    int slot16 = wn*4 + (lane & 3);
    #pragma unroll
    for (int mf = 0; mf < 4; mf++)
        #pragma unroll
        for (int h = 0; h < 2; h++) {
            int s = mf*2 + h;
            int r = wm*64 + mf*16 + (lane >> 2) + h*8;
            redV[(r*16 + slot16)*2 + 0] = bv0[s];
            redV[(r*16 + slot16)*2 + 1] = bv1[s];
            redI[(r*16 + slot16)*2 + 0] = bi0[s];
            redI[(r*16 + slot16)*2 + 1] = bi1[s];
        }
    __syncthreads();
    if (tid < 128) {
        float b0 = 3.4e38f, b1v = 3.4e38f; int i0 = 0, i1 = 0;
        #pragma unroll
        for (int s = 0; s < 32; s++) {
            float v = redV[tid*32 + s]; int iv = redI[tid*32 + s];
            if (v < b0 || (v == b0 && iv < i0)) { b1v = b0; i1 = i0; b0 = v; i0 = iv; }
            else if ((v < b1v || (v == b1v && iv < i1)) && iv != i0) { b1v = v; i1 = iv; }
        }
        g_cand[tokbase + tid] = make_int2(i0, i1);
    }
}

// =====================================================================
// Exact fp32 rescore of the two candidates -> final ids
// =====================================================================
__global__ void k_rescore(const float* __restrict__ x, float* __restrict__ out_ids_f) {
    int w = threadIdx.x >> 5, lane = threadIdx.x & 31;
    int t = blockIdx.x*8 + w;
    int l = (t / SDIM) % LDIM;
    int2 c = g_cand[t];
    const float* xr = x + (size_t)t*DDIM;
    const float* e0 = g_embedT + ((size_t)l*EDIM + c.x)*DDIM;
    const float* e1 = g_embedT + ((size_t)l*EDIM + c.y)*DDIM;
    float d0 = 0.f, d1 = 0.f;
    #pragma unroll
    for (int i = 0; i < 8; i++) {
        float xv = xr[lane + 32*i];
        d0 += xv * e0[lane + 32*i];
        d1 += xv * e1[lane + 32*i];
    }
    #pragma unroll
    for (int o = 16; o > 0; o >>= 1) {
        d0 += __shfl_down_sync(0xffffffffu, d0, o);
        d1 += __shfl_down_sync(0xffffffffu, d1, o);
    }
    if (lane == 0) {
        const float* en = g_enorm + l*EDIM;
        float s0 = fmaf(-2.0f, d0, en[c.x]);
        float s1 = fmaf(-2.0f, d1, en[c.y]);
        int best = (s1 < s0 || (s1 == s0 && c.y < c.x)) ? c.y : c.x;
        g_ids[t] = best;
        out_ids_f[t] = (float)best;
    }
}

// =====================================================================
// scatter / tail kernels (unchanged, known-good)
// =====================================================================
__global__ void k_scatter(const float* __restrict__ x, float* __restrict__ out) {
    int t = blockIdx.x;
    int l = (t / SDIM) % LDIM;
    int e = g_ids[t];
    int d = threadIdx.x;

    float xv = x[(size_t)t*DDIM + d];
    float qv = g_embedT[((size_t)l*EDIM + e)*DDIM + d];
    out[(size_t)t*DDIM + d] = qv;

    long long fx = llrint((double)xv * 4294967296.0);
    atomicAdd((unsigned long long*)&g_sum[((size_t)l*DDIM + d)*EDIM + e],
              (unsigned long long)fx);
    if (d == 0) atomicAdd(&g_counts[l*EDIM + e], 1);

    if (l == LDIM - 1) {
        __shared__ long long sred[8];
        float df = (qv - xv)*(qv - xv);
        long long fd = llrint((double)df * 1048576.0);
        #pragma unroll
        for (int o = 16; o > 0; o >>= 1) fd += __shfl_down_sync(0xffffffffu, fd, o);
        if ((threadIdx.x & 31) == 0) sred[threadIdx.x >> 5] = fd;
        __syncthreads();
        if (threadIdx.x == 0) {
            long long s = 0;
            #pragma unroll
            for (int w = 0; w < 8; w++) s += sred[w];
            atomicAdd(&g_diffacc, (unsigned long long)s);
        }
    }
}

__global__ void k_ncs(const float* __restrict__ cs_in,
                      float* __restrict__ out_ncs, float* __restrict__ out_diff) {
    int l = blockIdx.x;
    __shared__ float red[32];
    float local = 0.f;
    for (int e = threadIdx.x; e < EDIM; e += blockDim.x) {
        float v = 0.999f*cs_in[l*EDIM+e] + 0.001f*(float)g_counts[l*EDIM+e];
        out_ncs[l*EDIM+e] = v;
        local += v;
    }
    #pragma unroll
    for (int o = 16; o > 0; o >>= 1) local += __shfl_down_sync(0xffffffffu, local, o);
    if ((threadIdx.x & 31) == 0) red[threadIdx.x >> 5] = local;
    __syncthreads();
    if (threadIdx.x < 32) {
        float v = red[threadIdx.x];
        #pragma unroll
        for (int o = 16; o > 0; o >>= 1) v += __shfl_down_sync(0xffffffffu, v, o);
        if (threadIdx.x == 0) g_nvals[l] = v;
    }
    if (l == 0 && threadIdx.x == 0) {
        double dsum = (double)(long long)g_diffacc * (1.0/1048576.0);
        out_diff[0] = (float)(2.0 * (dsum / (double)((size_t)BDIM*SDIM*DDIM)) / (double)LDIM);
    }
}

__global__ void k_final(const float* __restrict__ embed_avg,
                        const float* __restrict__ out_ncs,
                        float* __restrict__ out_ne, float* __restrict__ out_nea) {
    size_t i = (size_t)blockIdx.x*blockDim.x + threadIdx.x;
    int e = (int)(i % EDIM);
    int l = (int)(i / ((size_t)DDIM*EDIM));
    float sum = (float)((double)g_sum[i] * (1.0/4294967296.0));
    float nea = 0.999f*embed_avg[i] + 0.001f*sum;
    out_nea[i] = nea;
    float ncs = out_ncs[l*EDIM + e];
    float n   = g_nvals[l];
    float cs  = (ncs + 1e-5f) / (n + 0.02048f) * n;
    out_ne[i] = nea / cs;
}

// =====================================================================
extern "C" void kernel_launch(void* const* d_in, const int* in_sizes, int n_in,
                              void* d_out, int out_size) {
    const float* x     = (const float*)d_in[0];
    const float* embed = (const float*)d_in[1];
    const float* csz   = (const float*)d_in[2];
    const float* eavg  = (const float*)d_in[3];

    float* out      = (float*)d_out;
    float* out_main = out;
    float* out_diff = out + (size_t)33554432;
    float* out_ids  = out + (size_t)33554433;
    float* out_ne   = out_ids + (size_t)131072;
    float* out_ncs  = out_ne  + (size_t)4194304;
    float* out_nea  = out_ncs + (size_t)16384;

    cudaFuncSetAttribute(k_assign_mma, cudaFuncAttributeMaxDynamicSharedMemorySize,
                         SMEM_TOTAL);

    void *pSum, *pCnt, *pDiff;
    cudaGetSymbolAddress(&pSum,  g_sum);
    cudaGetSymbolAddress(&pCnt,  g_counts);
    cudaGetSymbolAddress(&pDiff, g_diffacc);
    cudaMemsetAsync(pSum,  0, (size_t)LDIM*DDIM*EDIM*sizeof(long long));
    cudaMemsetAsync(pCnt,  0, (size_t)LDIM*EDIM*sizeof(int));
    cudaMemsetAsync(pDiff, 0, sizeof(unsigned long long));

    dim3 tb(32, 8);
    k_enorm<<<(LDIM*EDIM)/256, 256>>>(embed);
    k_expand_x<<<NTOK, 128>>>(x);
    k_expand_e<<<dim3(EDIM/32, DDIM/32, LDIM), tb>>>(embed);
    k_assign_mma<<<dim3(TOKL/128, LDIM), 256, SMEM_TOTAL>>>(0);
    k_rescore<<<NTOK/8, 256>>>(x, out_ids);
    k_scatter<<<NTOK, 256>>>(x, out_main);
    k_ncs<<<LDIM, 1024>>>(csz, out_ncs, out_diff);
    k_final<<<(unsigned)(((size_t)LDIM*DDIM*EDIM)/256), 256>>>(eavg, out_ncs, out_ne, out_nea);
}

// round 9
// speedup vs baseline: 1.1156x; 1.1156x over previous
#include <cuda_runtime.h>
#include <cuda_bf16.h>
#include <cstdint>
#include <math.h>

#define BDIM 32
#define LDIM 8
#define SDIM 512
#define DDIM 256
#define EDIM 2048
#define NTOK (BDIM*LDIM*SDIM)   /* 131072 */
#define TOKL (BDIM*SDIM)        /* 16384 tokens per l */

// ---- device scratch ----
__device__ float      g_embedT[(size_t)LDIM*EDIM*DDIM];   // (L,E,D) fp32 codebook
__device__ float      g_enorm [(size_t)LDIM*EDIM];        // ||e||^2 fp32
__device__ int        g_ids   [NTOK];
__device__ int2       g_cand  [NTOK];                     // top-2 approx candidates
__device__ int        g_counts[(size_t)LDIM*EDIM];
__device__ long long  g_sum   [(size_t)LDIM*DDIM*EDIM];
__device__ unsigned long long g_diffacc;
__device__ float      g_nvals [LDIM];
// bf16 2-split planes
__device__ unsigned short g_A1[(size_t)NTOK*DDIM];
__device__ unsigned short g_A2[(size_t)NTOK*DDIM];
__device__ unsigned short g_B1[(size_t)LDIM*EDIM*DDIM];
__device__ unsigned short g_B2[(size_t)LDIM*EDIM*DDIM];

// =====================================================================
__device__ __forceinline__ uint32_t smem_addr_u32(const void* p) {
    uint32_t a;
    asm("{ .reg .u64 t; cvta.to.shared.u64 t, %1; cvt.u32.u64 %0, t; }" : "=r"(a) : "l"(p));
    return a;
}
__device__ __forceinline__ void cpasync16(uint32_t s, const void* g) {
    asm volatile("cp.async.cg.shared.global [%0], [%1], 16;" :: "r"(s), "l"(g));
}
#define CP_COMMIT() asm volatile("cp.async.commit_group;" ::: "memory")
#define CP_WAIT(n)  asm volatile("cp.async.wait_group %0;" :: "n"(n) : "memory")

__device__ __forceinline__ void ldsm4(uint32_t* r, uint32_t addr) {
    asm volatile("ldmatrix.sync.aligned.m8n8.x4.shared.b16 {%0,%1,%2,%3}, [%4];"
        : "=r"(r[0]), "=r"(r[1]), "=r"(r[2]), "=r"(r[3]) : "r"(addr));
}
__device__ __forceinline__ void mma16816(float* c, const uint32_t* a, uint32_t b0, uint32_t b1) {
    asm volatile("mma.sync.aligned.m16n8k16.row.col.f32.bf16.bf16.f32 "
        "{%0,%1,%2,%3}, {%4,%5,%6,%7}, {%8,%9}, {%0,%1,%2,%3};"
        : "+f"(c[0]), "+f"(c[1]), "+f"(c[2]), "+f"(c[3])
        : "r"(a[0]), "r"(a[1]), "r"(a[2]), "r"(a[3]), "r"(b0), "r"(b1));
}

__device__ __forceinline__ void split2(float v, unsigned short& a, unsigned short& b) {
    __nv_bfloat16 h1 = __float2bfloat16(v);
    float r1 = v - __bfloat162float(h1);
    __nv_bfloat16 h2 = __float2bfloat16(r1);
    a = __bfloat16_as_ushort(h1);
    b = __bfloat16_as_ushort(h2);
}

// Expand x -> A1, A2
__global__ void k_expand_x(const float* __restrict__ x) {
    int t = blockIdx.x;
    int i = threadIdx.x;           // 128 threads, 2 d each
    float2 v = *(const float2*)(x + (size_t)t*DDIM + 2*i);
    unsigned short a0,b0, a1,b1;
    split2(v.x, a0, b0);
    split2(v.y, a1, b1);
    size_t o = (size_t)t*(DDIM/2) + i;
    ((uint32_t*)g_A1)[o] = (uint32_t)a0 | ((uint32_t)a1 << 16);
    ((uint32_t*)g_A2)[o] = (uint32_t)b0 | ((uint32_t)b1 << 16);
}

// Transpose + expand embed -> B1, B2 + fp32 g_embedT
__global__ void k_expand_e(const float* __restrict__ embed) {
    __shared__ float tile[32][33];
    int l  = blockIdx.z;
    int e0 = blockIdx.x * 32;
    int d0 = blockIdx.y * 32;
    int tx = threadIdx.x, ty = threadIdx.y;   // 32 x 8
    const float* src = embed + (size_t)l*DDIM*EDIM;
    #pragma unroll
    for (int i = ty; i < 32; i += 8)
        tile[i][tx] = src[(size_t)(d0+i)*EDIM + e0 + tx];
    __syncthreads();
    #pragma unroll
    for (int i = ty; i < 32; i += 8) {
        float v = tile[tx][i];
        unsigned short h1, h2;
        split2(v, h1, h2);
        size_t idx = ((size_t)(l*EDIM + e0 + i))*DDIM + (d0 + tx);
        g_B1[idx] = h1; g_B2[idx] = h2;
        g_embedT[idx] = v;
    }
}

__global__ void k_enorm(const float* __restrict__ embed) {
    int idx = blockIdx.x*blockDim.x + threadIdx.x;
    int l = idx / EDIM, e = idx % EDIM;
    const float* src = embed + (size_t)l*DDIM*EDIM + e;
    float s = 0.f;
    #pragma unroll 8
    for (int d = 0; d < DDIM; d++) {
        float v = src[(size_t)d*EDIM];
        s += v*v;
    }
    g_enorm[idx] = s;
}

// =====================================================================
// HMMA fused GEMM + approx top-2. 128 tokens x 2048 codes per CTA.
// Round-6 loop skeleton (ONE barrier per slab, depth-1 double buffer) with
// k-slab 64: half the barriers/waits. Row stride 144B (odd 16B phase ->
// conflict-free ldmatrix). 3 products A1B1+A1B2+A2B1.
// Stage: A1@0(18432) A2@18432 B1@36864(36864) B2@73728; STAGE=110592.
// FIX vs round 8: B ldmatrix fragment stride is 16 rows = 2304B (was 1152).
// =====================================================================
#define ST_A2   18432
#define ST_B1   36864
#define ST_B2   73728
#define STAGE   110592
#define SMEM_TOTAL (2*STAGE)

__device__ __forceinline__ void load_slab(uint32_t dst,
        const unsigned short* A1r, const unsigned short* A2r,
        const unsigned short* B1r, const unsigned short* B2r, int g, int tid) {
    int n0 = (g >> 2) << 8, kcol = (g & 3) << 6;
    #pragma unroll
    for (int it = 0; it < 4; it++) {          // A planes: 1024 chunks each
        int c = it*256 + tid, row = c >> 3, q = c & 7;
        const size_t go = (size_t)row*DDIM + kcol + q*8;
        uint32_t so = row*144 + q*16;
        cpasync16(dst + so,         A1r + go);
        cpasync16(dst + ST_A2 + so, A2r + go);
    }
    #pragma unroll
    for (int it = 0; it < 8; it++) {          // B planes: 2048 chunks each
        int c = it*256 + tid, row = c >> 3, q = c & 7;
        const size_t go = (size_t)(n0 + row)*DDIM + kcol + q*8;
        uint32_t so = row*144 + q*16;
        cpasync16(dst + ST_B1 + so, B1r + go);
        cpasync16(dst + ST_B2 + so, B2r + go);
    }
}

__global__ void __launch_bounds__(256)
k_assign_mma(int dummy) {
    extern __shared__ unsigned char smem[];
    const uint32_t sb = smem_addr_u32(smem);
    int tid = threadIdx.x, lane = tid & 31, wid = tid >> 5;
    int wm = wid >> 2, wn = wid & 3;
    int l  = blockIdx.y;
    int r0 = blockIdx.x * 128;
    int b = r0 >> 9, s0 = r0 & 511;
    size_t tokbase = ((size_t)(b*LDIM + l)*SDIM + s0);

    const unsigned short* A1r = g_A1 + tokbase*DDIM;
    const unsigned short* A2r = g_A2 + tokbase*DDIM;
    const unsigned short* B1r = g_B1 + (size_t)l*EDIM*DDIM;
    const unsigned short* B2r = g_B2 + (size_t)l*EDIM*DDIM;
    const float* en = g_enorm + l*EDIM;

    // prologue: slabs 0 and 1 in flight
    load_slab(sb,         A1r, A2r, B1r, B2r, 0, tid); CP_COMMIT();
    load_slab(sb + STAGE, A1r, A2r, B1r, B2r, 1, tid); CP_COMMIT();

    float bv0[8], bv1[8]; int bi0[8], bi1[8];
    #pragma unroll
    for (int i = 0; i < 8; i++) { bv0[i] = 3.4e38f; bv1[i] = 3.4e38f; bi0[i] = 0; bi1[i] = 0; }

    const uint32_t aAddr = (uint32_t)((wm*64 + (lane & 15))*144 + (lane >> 4)*16);
    const uint32_t bAddr = (uint32_t)(ST_B1 + (wn*64 + (lane & 7) + ((lane >> 4) & 1)*8)*144
                                      + ((lane >> 3) & 1)*16);
    float acc[4][8][4];

    for (int g = 0; g < 32; g++) {
        int ks = g & 3;
        if (ks == 0) {
            #pragma unroll
            for (int mf = 0; mf < 4; mf++)
                #pragma unroll
                for (int nf = 0; nf < 8; nf++)
                    #pragma unroll
                    for (int q = 0; q < 4; q++) acc[mf][nf][q] = 0.f;
        }
        if (g == 31) { CP_WAIT(0); } else { CP_WAIT(1); }
        __syncthreads();
        if (g + 1 < 32) {
            load_slab(sb + ((g+1) & 1)*STAGE, A1r, A2r, B1r, B2r, g + 1, tid);
            CP_COMMIT();
        }
        uint32_t stB = sb + (g & 1)*STAGE;
        uint32_t aB = stB + aAddr;
        uint32_t bB = stB + bAddr;
        #pragma unroll
        for (int kq = 0; kq < 4; kq++) {
            uint32_t a[4][4], bf[4][4], bf2[4][4];
            #pragma unroll
            for (int mf = 0; mf < 4; mf++) ldsm4(a[mf],   aB + mf*2304 + kq*32);
            #pragma unroll
            for (int nf = 0; nf < 4; nf++) ldsm4(bf[nf],  bB + nf*2304 + kq*32);
            #pragma unroll
            for (int nf = 0; nf < 4; nf++) ldsm4(bf2[nf], bB + (ST_B2-ST_B1) + nf*2304 + kq*32);
            #pragma unroll
            for (int mf = 0; mf < 4; mf++)
                #pragma unroll
                for (int nf = 0; nf < 4; nf++) {
                    mma16816(acc[mf][2*nf],   a[mf], bf[nf][0],  bf[nf][1]);
                    mma16816(acc[mf][2*nf+1], a[mf], bf[nf][2],  bf[nf][3]);
                    mma16816(acc[mf][2*nf],   a[mf], bf2[nf][0], bf2[nf][1]);
                    mma16816(acc[mf][2*nf+1], a[mf], bf2[nf][2], bf2[nf][3]);
                }
            #pragma unroll
            for (int mf = 0; mf < 4; mf++) ldsm4(a[mf], aB + ST_A2 + mf*2304 + kq*32);
            #pragma unroll
            for (int mf = 0; mf < 4; mf++)
                #pragma unroll
                for (int nf = 0; nf < 4; nf++) {
                    mma16816(acc[mf][2*nf],   a[mf], bf[nf][0], bf[nf][1]);
                    mma16816(acc[mf][2*nf+1], a[mf], bf[nf][2], bf[nf][3]);
                }
        }
        if (ks == 3) {
            int n0 = (g >> 2) << 8;
            #pragma unroll
            for (int nf = 0; nf < 8; nf++) {
                int col = n0 + wn*64 + nf*8 + 2*(lane & 3);
                float e0 = en[col], e1 = en[col + 1];
                #pragma unroll
                for (int mf = 0; mf < 4; mf++)
                    #pragma unroll
                    for (int h = 0; h < 2; h++) {
                        int s = mf*2 + h;
                        float v0 = fmaf(-2.0f, acc[mf][nf][2*h],     e0);
                        float v1 = fmaf(-2.0f, acc[mf][nf][2*h + 1], e1);
                        if (v0 < bv0[s]) { bv1[s]=bv0[s]; bi1[s]=bi0[s]; bv0[s]=v0; bi0[s]=col; }
                        else if (v0 < bv1[s]) { bv1[s]=v0; bi1[s]=col; }
                        if (v1 < bv0[s]) { bv1[s]=bv0[s]; bi1[s]=bi0[s]; bv0[s]=v1; bi0[s]=col+1; }
                        else if (v1 < bv1[s]) { bv1[s]=v1; bi1[s]=col+1; }
                    }
            }
        }
    }

    __syncthreads();
    float* redV = (float*)smem;                 // [128][16][2]
    int*   redI = (int*)(smem + 16384);
    int slot16 = wn*4 + (lane & 3);
    #pragma unroll
    for (int mf = 0; mf < 4; mf++)
        #pragma unroll
        for (int h = 0; h < 2; h++) {
            int s = mf*2 + h;
            int r = wm*64 + mf*16 + (lane >> 2) + h*8;
            redV[(r*16 + slot16)*2 + 0] = bv0[s];
            redV[(r*16 + slot16)*2 + 1] = bv1[s];
            redI[(r*16 + slot16)*2 + 0] = bi0[s];
            redI[(r*16 + slot16)*2 + 1] = bi1[s];
        }
    __syncthreads();
    if (tid < 128) {
        float b0 = 3.4e38f, b1v = 3.4e38f; int i0 = 0, i1 = 0;
        #pragma unroll
        for (int s = 0; s < 32; s++) {
            float v = redV[tid*32 + s]; int iv = redI[tid*32 + s];
            if (v < b0 || (v == b0 && iv < i0)) { b1v = b0; i1 = i0; b0 = v; i0 = iv; }
            else if ((v < b1v || (v == b1v && iv < i1)) && iv != i0) { b1v = v; i1 = iv; }
        }
        g_cand[tokbase + tid] = make_int2(i0, i1);
    }
}

// =====================================================================
// Exact fp32 rescore of the two candidates -> final ids
// =====================================================================
__global__ void k_rescore(const float* __restrict__ x, float* __restrict__ out_ids_f) {
    int w = threadIdx.x >> 5, lane = threadIdx.x & 31;
    int t = blockIdx.x*8 + w;
    int l = (t / SDIM) % LDIM;
    int2 c = g_cand[t];
    const float* xr = x + (size_t)t*DDIM;
    const float* e0 = g_embedT + ((size_t)l*EDIM + c.x)*DDIM;
    const float* e1 = g_embedT + ((size_t)l*EDIM + c.y)*DDIM;
    float d0 = 0.f, d1 = 0.f;
    #pragma unroll
    for (int i = 0; i < 8; i++) {
        float xv = xr[lane + 32*i];
        d0 += xv * e0[lane + 32*i];
        d1 += xv * e1[lane + 32*i];
    }
    #pragma unroll
    for (int o = 16; o > 0; o >>= 1) {
        d0 += __shfl_down_sync(0xffffffffu, d0, o);
        d1 += __shfl_down_sync(0xffffffffu, d1, o);
    }
    if (lane == 0) {
        const float* en = g_enorm + l*EDIM;
        float s0 = fmaf(-2.0f, d0, en[c.x]);
        float s1 = fmaf(-2.0f, d1, en[c.y]);
        int best = (s1 < s0 || (s1 == s0 && c.y < c.x)) ? c.y : c.x;
        g_ids[t] = best;
        out_ids_f[t] = (float)best;
    }
}

// =====================================================================
// scatter / tail kernels (unchanged, known-good)
// =====================================================================
__global__ void k_scatter(const float* __restrict__ x, float* __restrict__ out) {
    int t = blockIdx.x;
    int l = (t / SDIM) % LDIM;
    int e = g_ids[t];
    int d = threadIdx.x;

    float xv = x[(size_t)t*DDIM + d];
    float qv = g_embedT[((size_t)l*EDIM + e)*DDIM + d];
    out[(size_t)t*DDIM + d] = qv;

    long long fx = llrint((double)xv * 4294967296.0);
    atomicAdd((unsigned long long*)&g_sum[((size_t)l*DDIM + d)*EDIM + e],
              (unsigned long long)fx);
    if (d == 0) atomicAdd(&g_counts[l*EDIM + e], 1);

    if (l == LDIM - 1) {
        __shared__ long long sred[8];
        float df = (qv - xv)*(qv - xv);
        long long fd = llrint((double)df * 1048576.0);
        #pragma unroll
        for (int o = 16; o > 0; o >>= 1) fd += __shfl_down_sync(0xffffffffu, fd, o);
        if ((threadIdx.x & 31) == 0) sred[threadIdx.x >> 5] = fd;
        __syncthreads();
        if (threadIdx.x == 0) {
            long long s = 0;
            #pragma unroll
            for (int w = 0; w < 8; w++) s += sred[w];
            atomicAdd(&g_diffacc, (unsigned long long)s);
        }
    }
}

__global__ void k_ncs(const float* __restrict__ cs_in,
                      float* __restrict__ out_ncs, float* __restrict__ out_diff) {
    int l = blockIdx.x;
    __shared__ float red[32];
    float local = 0.f;
    for (int e = threadIdx.x; e < EDIM; e += blockDim.x) {
        float v = 0.999f*cs_in[l*EDIM+e] + 0.001f*(float)g_counts[l*EDIM+e];
        out_ncs[l*EDIM+e] = v;
        local += v;
    }
    #pragma unroll
    for (int o = 16; o > 0; o >>= 1) local += __shfl_down_sync(0xffffffffu, local, o);
    if ((threadIdx.x & 31) == 0) red[threadIdx.x >> 5] = local;
    __syncthreads();
    if (threadIdx.x < 32) {
        float v = red[threadIdx.x];
        #pragma unroll
        for (int o = 16; o > 0; o >>= 1) v += __shfl_down_sync(0xffffffffu, v, o);
        if (threadIdx.x == 0) g_nvals[l] = v;
    }
    if (l == 0 && threadIdx.x == 0) {
        double dsum = (double)(long long)g_diffacc * (1.0/1048576.0);
        out_diff[0] = (float)(2.0 * (dsum / (double)((size_t)BDIM*SDIM*DDIM)) / (double)LDIM);
    }
}

__global__ void k_final(const float* __restrict__ embed_avg,
                        const float* __restrict__ out_ncs,
                        float* __restrict__ out_ne, float* __restrict__ out_nea) {
    size_t i = (size_t)blockIdx.x*blockDim.x + threadIdx.x;
    int e = (int)(i % EDIM);
    int l = (int)(i / ((size_t)DDIM*EDIM));
    float sum = (float)((double)g_sum[i] * (1.0/4294967296.0));
    float nea = 0.999f*embed_avg[i] + 0.001f*sum;
    out_nea[i] = nea;
    float ncs = out_ncs[l*EDIM + e];
    float n   = g_nvals[l];
    float cs  = (ncs + 1e-5f) / (n + 0.02048f) * n;
    out_ne[i] = nea / cs;
}

// =====================================================================
extern "C" void kernel_launch(void* const* d_in, const int* in_sizes, int n_in,
                              void* d_out, int out_size) {
    const float* x     = (const float*)d_in[0];
    const float* embed = (const float*)d_in[1];
    const float* csz   = (const float*)d_in[2];
    const float* eavg  = (const float*)d_in[3];

    float* out      = (float*)d_out;
    float* out_main = out;
    float* out_diff = out + (size_t)33554432;
    float* out_ids  = out + (size_t)33554433;
    float* out_ne   = out_ids + (size_t)131072;
    float* out_ncs  = out_ne  + (size_t)4194304;
    float* out_nea  = out_ncs + (size_t)16384;

    cudaFuncSetAttribute(k_assign_mma, cudaFuncAttributeMaxDynamicSharedMemorySize,
                         SMEM_TOTAL);

    void *pSum, *pCnt, *pDiff;
    cudaGetSymbolAddress(&pSum,  g_sum);
    cudaGetSymbolAddress(&pCnt,  g_counts);
    cudaGetSymbolAddress(&pDiff, g_diffacc);
    cudaMemsetAsync(pSum,  0, (size_t)LDIM*DDIM*EDIM*sizeof(long long));
    cudaMemsetAsync(pCnt,  0, (size_t)LDIM*EDIM*sizeof(int));
    cudaMemsetAsync(pDiff, 0, sizeof(unsigned long long));

    dim3 tb(32, 8);
    k_enorm<<<(LDIM*EDIM)/256, 256>>>(embed);
    k_expand_x<<<NTOK, 128>>>(x);
    k_expand_e<<<dim3(EDIM/32, DDIM/32, LDIM), tb>>>(embed);
    k_assign_mma<<<dim3(TOKL/128, LDIM), 256, SMEM_TOTAL>>>(0);
    k_rescore<<<NTOK/8, 256>>>(x, out_ids);
    k_scatter<<<NTOK, 256>>>(x, out_main);
    k_ncs<<<LDIM, 1024>>>(csz, out_ncs, out_diff);
    k_final<<<(unsigned)(((size_t)LDIM*DDIM*EDIM)/256), 256>>>(eavg, out_ncs, out_ne, out_nea);
}

// round 10
// speedup vs baseline: 1.1859x; 1.0630x over previous
#include <cuda_runtime.h>
#include <cuda_bf16.h>
#include <cstdint>
#include <math.h>

#define BDIM 32
#define LDIM 8
#define SDIM 512
#define DDIM 256
#define EDIM 2048
#define NTOK (BDIM*LDIM*SDIM)   /* 131072 */
#define TOKL (BDIM*SDIM)        /* 16384 tokens per l */

// ---- device scratch ----
__device__ float      g_embedT[(size_t)LDIM*EDIM*DDIM];   // (L,E,D) fp32 codebook
__device__ float      g_enorm [(size_t)LDIM*EDIM];        // ||e||^2 fp32
__device__ int        g_ids   [NTOK];
__device__ int2       g_cand  [NTOK];                     // top-2 approx candidates
__device__ int        g_counts[(size_t)LDIM*EDIM];
__device__ long long  g_sum   [(size_t)LDIM*DDIM*EDIM];
__device__ unsigned long long g_diffacc;
__device__ float      g_nvals [LDIM];
// bf16 2-split planes
__device__ unsigned short g_A1[(size_t)NTOK*DDIM];
__device__ unsigned short g_A2[(size_t)NTOK*DDIM];
__device__ unsigned short g_B1[(size_t)LDIM*EDIM*DDIM];
__device__ unsigned short g_B2[(size_t)LDIM*EDIM*DDIM];

// =====================================================================
__device__ __forceinline__ uint32_t smem_addr_u32(const void* p) {
    uint32_t a;
    asm("{ .reg .u64 t; cvta.to.shared.u64 t, %1; cvt.u32.u64 %0, t; }" : "=r"(a) : "l"(p));
    return a;
}
__device__ __forceinline__ void cpasync16(uint32_t s, const void* g) {
    asm volatile("cp.async.cg.shared.global [%0], [%1], 16;" :: "r"(s), "l"(g));
}
#define CP_COMMIT() asm volatile("cp.async.commit_group;" ::: "memory")
#define CP_WAIT(n)  asm volatile("cp.async.wait_group %0;" :: "n"(n) : "memory")

__device__ __forceinline__ void ldsm4(uint32_t* r, uint32_t addr) {
    asm volatile("ldmatrix.sync.aligned.m8n8.x4.shared.b16 {%0,%1,%2,%3}, [%4];"
        : "=r"(r[0]), "=r"(r[1]), "=r"(r[2]), "=r"(r[3]) : "r"(addr));
}
__device__ __forceinline__ void mma16816(float* c, const uint32_t* a, uint32_t b0, uint32_t b1) {
    asm volatile("mma.sync.aligned.m16n8k16.row.col.f32.bf16.bf16.f32 "
        "{%0,%1,%2,%3}, {%4,%5,%6,%7}, {%8,%9}, {%0,%1,%2,%3};"
        : "+f"(c[0]), "+f"(c[1]), "+f"(c[2]), "+f"(c[3])
        : "r"(a[0]), "r"(a[1]), "r"(a[2]), "r"(a[3]), "r"(b0), "r"(b1));
}

__device__ __forceinline__ void split2(float v, unsigned short& a, unsigned short& b) {
    __nv_bfloat16 h1 = __float2bfloat16(v);
    float r1 = v - __bfloat162float(h1);
    __nv_bfloat16 h2 = __float2bfloat16(r1);
    a = __bfloat16_as_ushort(h1);
    b = __bfloat16_as_ushort(h2);
}

// Expand x -> A1, A2
__global__ void k_expand_x(const float* __restrict__ x) {
    int t = blockIdx.x;
    int i = threadIdx.x;           // 128 threads, 2 d each
    float2 v = *(const float2*)(x + (size_t)t*DDIM + 2*i);
    unsigned short a0,b0, a1,b1;
    split2(v.x, a0, b0);
    split2(v.y, a1, b1);
    size_t o = (size_t)t*(DDIM/2) + i;
    ((uint32_t*)g_A1)[o] = (uint32_t)a0 | ((uint32_t)a1 << 16);
    ((uint32_t*)g_A2)[o] = (uint32_t)b0 | ((uint32_t)b1 << 16);
}

// Transpose + expand embed -> B1, B2 + fp32 g_embedT
__global__ void k_expand_e(const float* __restrict__ embed) {
    __shared__ float tile[32][33];
    int l  = blockIdx.z;
    int e0 = blockIdx.x * 32;
    int d0 = blockIdx.y * 32;
    int tx = threadIdx.x, ty = threadIdx.y;   // 32 x 8
    const float* src = embed + (size_t)l*DDIM*EDIM;
    #pragma unroll
    for (int i = ty; i < 32; i += 8)
        tile[i][tx] = src[(size_t)(d0+i)*EDIM + e0 + tx];
    __syncthreads();
    #pragma unroll
    for (int i = ty; i < 32; i += 8) {
        float v = tile[tx][i];
        unsigned short h1, h2;
        split2(v, h1, h2);
        size_t idx = ((size_t)(l*EDIM + e0 + i))*DDIM + (d0 + tx);
        g_B1[idx] = h1; g_B2[idx] = h2;
        g_embedT[idx] = v;
    }
}

__global__ void k_enorm(const float* __restrict__ embed) {
    int idx = blockIdx.x*blockDim.x + threadIdx.x;
    int l = idx / EDIM, e = idx % EDIM;
    const float* src = embed + (size_t)l*DDIM*EDIM + e;
    float s = 0.f;
    #pragma unroll 8
    for (int d = 0; d < DDIM; d++) {
        float v = src[(size_t)d*EDIM];
        s += v*v;
    }
    g_enorm[idx] = s;
}

// =====================================================================
// HMMA fused GEMM + approx top-2. 128 tokens x 2048 codes per CTA.
// 512 threads = 16 warps (4 M x 4 N), warp tile 32x64 -> 4 warps/SMSP for
// latency hiding; acc = 64 regs/thread, __launch_bounds__(512,1).
// k-slab 64, depth-1 double buffer, one barrier per slab. Row stride 144B.
// 3 products A1B1+A1B2+A2B1.
// Stage: A1@0(18432) A2@18432 B1@36864(36864) B2@73728; STAGE=110592.
// =====================================================================
#define ST_A2   18432
#define ST_B1   36864
#define ST_B2   73728
#define STAGE   110592
#define SMEM_TOTAL (2*STAGE)

__device__ __forceinline__ void load_slab(uint32_t dst,
        const unsigned short* A1r, const unsigned short* A2r,
        const unsigned short* B1r, const unsigned short* B2r, int g, int tid) {
    int n0 = (g >> 2) << 8, kcol = (g & 3) << 6;
    #pragma unroll
    for (int it = 0; it < 2; it++) {          // A planes: 1024 chunks each
        int c = it*512 + tid, row = c >> 3, q = c & 7;
        const size_t go = (size_t)row*DDIM + kcol + q*8;
        uint32_t so = row*144 + q*16;
        cpasync16(dst + so,         A1r + go);
        cpasync16(dst + ST_A2 + so, A2r + go);
    }
    #pragma unroll
    for (int it = 0; it < 4; it++) {          // B planes: 2048 chunks each
        int c = it*512 + tid, row = c >> 3, q = c & 7;
        const size_t go = (size_t)(n0 + row)*DDIM + kcol + q*8;
        uint32_t so = row*144 + q*16;
        cpasync16(dst + ST_B1 + so, B1r + go);
        cpasync16(dst + ST_B2 + so, B2r + go);
    }
}

__global__ void __launch_bounds__(512, 1)
k_assign_mma(int dummy) {
    extern __shared__ unsigned char smem[];
    const uint32_t sb = smem_addr_u32(smem);
    int tid = threadIdx.x, lane = tid & 31, wid = tid >> 5;
    int wm = wid >> 2, wn = wid & 3;          // 4 x 4 warp grid
    int l  = blockIdx.y;
    int r0 = blockIdx.x * 128;
    int b = r0 >> 9, s0 = r0 & 511;
    size_t tokbase = ((size_t)(b*LDIM + l)*SDIM + s0);

    const unsigned short* A1r = g_A1 + tokbase*DDIM;
    const unsigned short* A2r = g_A2 + tokbase*DDIM;
    const unsigned short* B1r = g_B1 + (size_t)l*EDIM*DDIM;
    const unsigned short* B2r = g_B2 + (size_t)l*EDIM*DDIM;
    const float* en = g_enorm + l*EDIM;

    // prologue: slabs 0 and 1 in flight
    load_slab(sb,         A1r, A2r, B1r, B2r, 0, tid); CP_COMMIT();
    load_slab(sb + STAGE, A1r, A2r, B1r, B2r, 1, tid); CP_COMMIT();

    float bv0[4], bv1[4]; int bi0[4], bi1[4];
    #pragma unroll
    for (int i = 0; i < 4; i++) { bv0[i] = 3.4e38f; bv1[i] = 3.4e38f; bi0[i] = 0; bi1[i] = 0; }

    const uint32_t aAddr = (uint32_t)((wm*32 + (lane & 15))*144 + (lane >> 4)*16);
    const uint32_t bAddr = (uint32_t)(ST_B1 + (wn*64 + (lane & 7) + ((lane >> 4) & 1)*8)*144
                                      + ((lane >> 3) & 1)*16);
    float acc[2][8][4];

    for (int g = 0; g < 32; g++) {
        int ks = g & 3;
        if (ks == 0) {
            #pragma unroll
            for (int mf = 0; mf < 2; mf++)
                #pragma unroll
                for (int nf = 0; nf < 8; nf++)
                    #pragma unroll
                    for (int q = 0; q < 4; q++) acc[mf][nf][q] = 0.f;
        }
        if (g == 31) { CP_WAIT(0); } else { CP_WAIT(1); }
        __syncthreads();
        if (g + 1 < 32) {
            load_slab(sb + ((g+1) & 1)*STAGE, A1r, A2r, B1r, B2r, g + 1, tid);
            CP_COMMIT();
        }
        uint32_t stB = sb + (g & 1)*STAGE;
        uint32_t aB = stB + aAddr;
        uint32_t bB = stB + bAddr;
        #pragma unroll
        for (int kq = 0; kq < 4; kq++) {
            uint32_t a[2][4], bf[4][4], bf2[4][4];
            #pragma unroll
            for (int mf = 0; mf < 2; mf++) ldsm4(a[mf],   aB + mf*2304 + kq*32);
            #pragma unroll
            for (int nf = 0; nf < 4; nf++) ldsm4(bf[nf],  bB + nf*2304 + kq*32);
            #pragma unroll
            for (int nf = 0; nf < 4; nf++) ldsm4(bf2[nf], bB + (ST_B2-ST_B1) + nf*2304 + kq*32);
            #pragma unroll
            for (int mf = 0; mf < 2; mf++)
                #pragma unroll
                for (int nf = 0; nf < 4; nf++) {
                    mma16816(acc[mf][2*nf],   a[mf], bf[nf][0],  bf[nf][1]);
                    mma16816(acc[mf][2*nf+1], a[mf], bf[nf][2],  bf[nf][3]);
                    mma16816(acc[mf][2*nf],   a[mf], bf2[nf][0], bf2[nf][1]);
                    mma16816(acc[mf][2*nf+1], a[mf], bf2[nf][2], bf2[nf][3]);
                }
            #pragma unroll
            for (int mf = 0; mf < 2; mf++) ldsm4(a[mf], aB + ST_A2 + mf*2304 + kq*32);
            #pragma unroll
            for (int mf = 0; mf < 2; mf++)
                #pragma unroll
                for (int nf = 0; nf < 4; nf++) {
                    mma16816(acc[mf][2*nf],   a[mf], bf[nf][0], bf[nf][1]);
                    mma16816(acc[mf][2*nf+1], a[mf], bf[nf][2], bf[nf][3]);
                }
        }
        if (ks == 3) {
            int n0 = (g >> 2) << 8;
            #pragma unroll
            for (int nf = 0; nf < 8; nf++) {
                int col = n0 + wn*64 + nf*8 + 2*(lane & 3);
                float e0 = en[col], e1 = en[col + 1];
                #pragma unroll
                for (int mf = 0; mf < 2; mf++)
                    #pragma unroll
                    for (int h = 0; h < 2; h++) {
                        int s = mf*2 + h;
                        float v0 = fmaf(-2.0f, acc[mf][nf][2*h],     e0);
                        float v1 = fmaf(-2.0f, acc[mf][nf][2*h + 1], e1);
                        if (v0 < bv0[s]) { bv1[s]=bv0[s]; bi1[s]=bi0[s]; bv0[s]=v0; bi0[s]=col; }
                        else if (v0 < bv1[s]) { bv1[s]=v0; bi1[s]=col; }
                        if (v1 < bv0[s]) { bv1[s]=bv0[s]; bi1[s]=bi0[s]; bv0[s]=v1; bi0[s]=col+1; }
                        else if (v1 < bv1[s]) { bv1[s]=v1; bi1[s]=col+1; }
                    }
            }
        }
    }

    __syncthreads();
    float* redV = (float*)smem;                 // [128][16][2]
    int*   redI = (int*)(smem + 16384);
    int slot16 = wn*4 + (lane & 3);
    #pragma unroll
    for (int mf = 0; mf < 2; mf++)
        #pragma unroll
        for (int h = 0; h < 2; h++) {
            int s = mf*2 + h;
            int r = wm*32 + mf*16 + (lane >> 2) + h*8;
            redV[(r*16 + slot16)*2 + 0] = bv0[s];
            redV[(r*16 + slot16)*2 + 1] = bv1[s];
            redI[(r*16 + slot16)*2 + 0] = bi0[s];
            redI[(r*16 + slot16)*2 + 1] = bi1[s];
        }
    __syncthreads();
    if (tid < 128) {
        float b0 = 3.4e38f, b1v = 3.4e38f; int i0 = 0, i1 = 0;
        #pragma unroll
        for (int s = 0; s < 32; s++) {
            float v = redV[tid*32 + s]; int iv = redI[tid*32 + s];
            if (v < b0 || (v == b0 && iv < i0)) { b1v = b0; i1 = i0; b0 = v; i0 = iv; }
            else if ((v < b1v || (v == b1v && iv < i1)) && iv != i0) { b1v = v; i1 = iv; }
        }
        g_cand[tokbase + tid] = make_int2(i0, i1);
    }
}

// =====================================================================
// Exact fp32 rescore of the two candidates -> final ids
// =====================================================================
__global__ void k_rescore(const float* __restrict__ x, float* __restrict__ out_ids_f) {
    int w = threadIdx.x >> 5, lane = threadIdx.x & 31;
    int t = blockIdx.x*8 + w;
    int l = (t / SDIM) % LDIM;
    int2 c = g_cand[t];
    const float* xr = x + (size_t)t*DDIM;
    const float* e0 = g_embedT + ((size_t)l*EDIM + c.x)*DDIM;
    const float* e1 = g_embedT + ((size_t)l*EDIM + c.y)*DDIM;
    float d0 = 0.f, d1 = 0.f;
    #pragma unroll
    for (int i = 0; i < 8; i++) {
        float xv = xr[lane + 32*i];
        d0 += xv * e0[lane + 32*i];
        d1 += xv * e1[lane + 32*i];
    }
    #pragma unroll
    for (int o = 16; o > 0; o >>= 1) {
        d0 += __shfl_down_sync(0xffffffffu, d0, o);
        d1 += __shfl_down_sync(0xffffffffu, d1, o);
    }
    if (lane == 0) {
        const float* en = g_enorm + l*EDIM;
        float s0 = fmaf(-2.0f, d0, en[c.x]);
        float s1 = fmaf(-2.0f, d1, en[c.y]);
        int best = (s1 < s0 || (s1 == s0 && c.y < c.x)) ? c.y : c.x;
        g_ids[t] = best;
        out_ids_f[t] = (float)best;
    }
}

// =====================================================================
// scatter / tail kernels (unchanged, known-good)
// =====================================================================
__global__ void k_scatter(const float* __restrict__ x, float* __restrict__ out) {
    int t = blockIdx.x;
    int l = (t / SDIM) % LDIM;
    int e = g_ids[t];
    int d = threadIdx.x;

    float xv = x[(size_t)t*DDIM + d];
    float qv = g_embedT[((size_t)l*EDIM + e)*DDIM + d];
    out[(size_t)t*DDIM + d] = qv;

    long long fx = llrint((double)xv * 4294967296.0);
    atomicAdd((unsigned long long*)&g_sum[((size_t)l*DDIM + d)*EDIM + e],
              (unsigned long long)fx);
    if (d == 0) atomicAdd(&g_counts[l*EDIM + e], 1);

    if (l == LDIM - 1) {
        __shared__ long long sred[8];
        float df = (qv - xv)*(qv - xv);
        long long fd = llrint((double)df * 1048576.0);
        #pragma unroll
        for (int o = 16; o > 0; o >>= 1) fd += __shfl_down_sync(0xffffffffu, fd, o);
        if ((threadIdx.x & 31) == 0) sred[threadIdx.x >> 5] = fd;
        __syncthreads();
        if (threadIdx.x == 0) {
            long long s = 0;
            #pragma unroll
            for (int w = 0; w < 8; w++) s += sred[w];
            atomicAdd(&g_diffacc, (unsigned long long)s);
        }
    }
}

__global__ void k_ncs(const float* __restrict__ cs_in,
                      float* __restrict__ out_ncs, float* __restrict__ out_diff) {
    int l = blockIdx.x;
    __shared__ float red[32];
    float local = 0.f;
    for (int e = threadIdx.x; e < EDIM; e += blockDim.x) {
        float v = 0.999f*cs_in[l*EDIM+e] + 0.001f*(float)g_counts[l*EDIM+e];
        out_ncs[l*EDIM+e] = v;
        local += v;
    }
    #pragma unroll
    for (int o = 16; o > 0; o >>= 1) local += __shfl_down_sync(0xffffffffu, local, o);
    if ((threadIdx.x & 31) == 0) red[threadIdx.x >> 5] = local;
    __syncthreads();
    if (threadIdx.x < 32) {
        float v = red[threadIdx.x];
        #pragma unroll
        for (int o = 16; o > 0; o >>= 1) v += __shfl_down_sync(0xffffffffu, v, o);
        if (threadIdx.x == 0) g_nvals[l] = v;
    }
    if (l == 0 && threadIdx.x == 0) {
        double dsum = (double)(long long)g_diffacc * (1.0/1048576.0);
        out_diff[0] = (float)(2.0 * (dsum / (double)((size_t)BDIM*SDIM*DDIM)) / (double)LDIM);
    }
}

__global__ void k_final(const float* __restrict__ embed_avg,
                        const float* __restrict__ out_ncs,
                        float* __restrict__ out_ne, float* __restrict__ out_nea) {
    size_t i = (size_t)blockIdx.x*blockDim.x + threadIdx.x;
    int e = (int)(i % EDIM);
    int l = (int)(i / ((size_t)DDIM*EDIM));
    float sum = (float)((double)g_sum[i] * (1.0/4294967296.0));
    float nea = 0.999f*embed_avg[i] + 0.001f*sum;
    out_nea[i] = nea;
    float ncs = out_ncs[l*EDIM + e];
    float n   = g_nvals[l];
    float cs  = (ncs + 1e-5f) / (n + 0.02048f) * n;
    out_ne[i] = nea / cs;
}

// =====================================================================
extern "C" void kernel_launch(void* const* d_in, const int* in_sizes, int n_in,
                              void* d_out, int out_size) {
    const float* x     = (const float*)d_in[0];
    const float* embed = (const float*)d_in[1];
    const float* csz   = (const float*)d_in[2];
    const float* eavg  = (const float*)d_in[3];

    float* out      = (float*)d_out;
    float* out_main = out;
    float* out_diff = out + (size_t)33554432;
    float* out_ids  = out + (size_t)33554433;
    float* out_ne   = out_ids + (size_t)131072;
    float* out_ncs  = out_ne  + (size_t)4194304;
    float* out_nea  = out_ncs + (size_t)16384;

    cudaFuncSetAttribute(k_assign_mma, cudaFuncAttributeMaxDynamicSharedMemorySize,
                         SMEM_TOTAL);

    void *pSum, *pCnt, *pDiff;
    cudaGetSymbolAddress(&pSum,  g_sum);
    cudaGetSymbolAddress(&pCnt,  g_counts);
    cudaGetSymbolAddress(&pDiff, g_diffacc);
    cudaMemsetAsync(pSum,  0, (size_t)LDIM*DDIM*EDIM*sizeof(long long));
    cudaMemsetAsync(pCnt,  0, (size_t)LDIM*EDIM*sizeof(int));
    cudaMemsetAsync(pDiff, 0, sizeof(unsigned long long));

    dim3 tb(32, 8);
    k_enorm<<<(LDIM*EDIM)/256, 256>>>(embed);
    k_expand_x<<<NTOK, 128>>>(x);
    k_expand_e<<<dim3(EDIM/32, DDIM/32, LDIM), tb>>>(embed);
    k_assign_mma<<<dim3(TOKL/128, LDIM), 512, SMEM_TOTAL>>>(0);
    k_rescore<<<NTOK/8, 256>>>(x, out_ids);
    k_scatter<<<NTOK, 256>>>(x, out_main);
    k_ncs<<<LDIM, 1024>>>(csz, out_ncs, out_diff);
    k_final<<<(unsigned)(((size_t)LDIM*DDIM*EDIM)/256), 256>>>(eavg, out_ncs, out_ne, out_nea);
}